// round 2
// baseline (speedup 1.0000x reference)
#include <cuda_runtime.h>

#define NB 65536
#define DD 128
#define SLOT (NB*DD)   // 8,388,608

// ---------------- scratch (static device globals; no allocation) ----------------
__device__ float g_Pa[SLOT];
__device__ float g_Pv[SLOT];
__device__ float g_Pl[SLOT];
__device__ float g_uni[SLOT];
__device__ float g_bi[SLOT];
__device__ float g_tri[SLOT];
__device__ float g_G[3*SLOT];    // gav/gal/gvl, later overwritten with a_v/a_l/v_l
__device__ float g_G2[6*SLOT];   // gf2 outputs (already n2-scaled+tanh'd)
__device__ float g_s[NB*16];     // per-row scalars

// ---------------- helpers ----------------
__device__ __forceinline__ float wsum(float x){
  #pragma unroll
  for (int o=16;o;o>>=1) x += __shfl_xor_sync(0xffffffffu, x, o);
  return x;
}
__device__ __forceinline__ float wmax(float x){
  #pragma unroll
  for (int o=16;o;o>>=1) x = fmaxf(x, __shfl_xor_sync(0xffffffffu, x, o));
  return x;
}
__device__ __forceinline__ float dot4(float4 a, float4 b){
  return a.x*b.x + a.y*b.y + a.z*b.z + a.w*b.w;
}
__device__ __forceinline__ float max4(float4 a){ return fmaxf(fmaxf(a.x,a.y),fmaxf(a.z,a.w)); }
__device__ __forceinline__ float sum4(float4 a){ return a.x+a.y+a.z+a.w; }

// ---------------- K1: rowwise pre (warp per row) ----------------
__global__ __launch_bounds__(256) void k1_pre(
    const float* __restrict__ L, const float* __restrict__ A,
    const float* __restrict__ V, const float* __restrict__ attw,
    const float* __restrict__ attb)
{
  int gw   = (int)((blockIdx.x*blockDim.x + threadIdx.x) >> 5);
  int lane = threadIdx.x & 31;
  size_t base = (size_t)gw*DD + lane*4;

  float4 av = *(const float4*)(A+base);
  float4 vv = *(const float4*)(V+base);
  float4 lv = *(const float4*)(L+base);
  float4 wv = *(const float4*)(attw + lane*4);
  float bb = attb[0];

  float sa = tanhf(wsum(dot4(av,wv)) + bb);
  float sv = tanhf(wsum(dot4(vv,wv)) + bb);
  float sl = tanhf(wsum(dot4(lv,wv)) + bb);

  float4 u;
  u.x = (sa*av.x + sv*vv.x + sl*lv.x)*(1.0f/3.0f);
  u.y = (sa*av.y + sv*vv.y + sl*lv.y)*(1.0f/3.0f);
  u.z = (sa*av.z + sv*vv.z + sl*lv.z)*(1.0f/3.0f);
  u.w = (sa*av.w + sv*vv.w + sl*lv.w)*(1.0f/3.0f);
  *(float4*)(g_uni+base) = u;

  // softmax(a)
  float m = wmax(max4(av));
  float4 pa = make_float4(expf(av.x-m),expf(av.y-m),expf(av.z-m),expf(av.w-m));
  float inv = 1.0f/wsum(sum4(pa));
  pa.x*=inv; pa.y*=inv; pa.z*=inv; pa.w*=inv;
  // softmax(v)
  m = wmax(max4(vv));
  float4 pv = make_float4(expf(vv.x-m),expf(vv.y-m),expf(vv.z-m),expf(vv.w-m));
  inv = 1.0f/wsum(sum4(pv));
  pv.x*=inv; pv.y*=inv; pv.z*=inv; pv.w*=inv;
  // softmax(l)
  m = wmax(max4(lv));
  float4 pl = make_float4(expf(lv.x-m),expf(lv.y-m),expf(lv.z-m),expf(lv.w-m));
  inv = 1.0f/wsum(sum4(pl));
  pl.x*=inv; pl.y*=inv; pl.z*=inv; pl.w*=inv;

  *(float4*)(g_Pa+base) = pa;
  *(float4*)(g_Pv+base) = pv;
  *(float4*)(g_Pl+base) = pl;

  float dav = wsum(dot4(pa,pv));
  float dal = wsum(dot4(pa,pl));
  float dvl = wsum(dot4(pv,pl));

  float sav = (sa+sv)/(dav+0.5f);
  float sal = (sa+sl)/(dal+0.5f);
  float svl = (sl+sv)/(dvl+0.5f);

  float m3 = fmaxf(sav,fmaxf(sal,svl));
  float e0 = expf(sav-m3), e1 = expf(sal-m3), e2 = expf(svl-m3);
  float r3 = 1.0f/(e0+e1+e2);

  if (lane==0){
    float* s = g_s + (size_t)gw*16;
    s[0]=sa; s[1]=sv; s[2]=sl;
    s[3]=sav; s[4]=sal; s[5]=svl;
    s[6]=e0*r3; s[7]=e1*r3; s[8]=e2*r3;
  }
}

// ---------------- fused 2-layer MLP (lrelu -> tanh [-> n2-scaled tanh]) ----------------
// CTA = 256 threads, TILE_M = 128 rows.  K=256 from concat(x1,x2), H=64, OUT=128.
__device__ __forceinline__ void mlp2(
    const float* __restrict__ x1, const float* __restrict__ x2,
    const float* __restrict__ w1, const float* __restrict__ b1,
    const float* __restrict__ w2, const float* __restrict__ b2,
    float* __restrict__ out, int row0, int n2slot)
{
  extern __shared__ float sm[];
  float* Xs  = sm;              // 128 x 65 = 8320
  float* Hs  = sm + 8320;       // 128 x 64 = 8192
  float* W1c = sm + 16512;      // 64 x 64  = 4096
  float* W2s = sm + 20608;      // 64 x 128 = 8192  -> total 28800 floats = 115200B

  int tid = threadIdx.x;
  // load W2 once
  #pragma unroll
  for (int i = tid*4; i < 8192; i += 1024)
    *(float4*)&W2s[i] = *(const float4*)&w2[i];

  int tc = tid & 15, tr = tid >> 4;
  int r0 = tr*8, c0 = tc*4, c8 = tc*8;

  float acc[8][4];
  #pragma unroll
  for (int i=0;i<8;i++){
    #pragma unroll
    for (int j=0;j<4;j++) acc[i][j]=0.f;
  }

  // -------- stage 1: H = lrelu(concat(x1,x2) @ W1 + b1) --------
  #pragma unroll 1
  for (int ch = 0; ch < 4; ch++){
    const float* src = (ch < 2) ? x1 : x2;
    int kc = (ch & 1)*64;
    __syncthreads();
    #pragma unroll
    for (int it=0; it<8; it++){
      int idx = tid*4 + it*1024;
      int r = idx>>6, kk = idx&63;
      float4 t = *(const float4*)(src + (size_t)(row0+r)*DD + kc + kk);
      float* d = &Xs[r*65 + kk];
      d[0]=t.x; d[1]=t.y; d[2]=t.z; d[3]=t.w;
    }
    #pragma unroll
    for (int it=0; it<4; it++){
      int idx = tid*4 + it*1024;
      *(float4*)&W1c[idx] = *(const float4*)&w1[ch*4096 + idx];
    }
    __syncthreads();
    #pragma unroll 4
    for (int k=0;k<64;k++){
      float4 wv = *(float4*)&W1c[k*64 + c0];
      #pragma unroll
      for (int i=0;i<8;i++){
        float xv = Xs[(r0+i)*65 + k];
        acc[i][0] += xv*wv.x; acc[i][1] += xv*wv.y;
        acc[i][2] += xv*wv.z; acc[i][3] += xv*wv.w;
      }
    }
  }
  __syncthreads();
  {
    float bb0=b1[c0], bb1=b1[c0+1], bb2=b1[c0+2], bb3=b1[c0+3];
    #pragma unroll
    for (int i=0;i<8;i++){
      float h0 = acc[i][0]+bb0; h0 = (h0>0.f)? h0 : 0.2f*h0;
      float h1 = acc[i][1]+bb1; h1 = (h1>0.f)? h1 : 0.2f*h1;
      float h2 = acc[i][2]+bb2; h2 = (h2>0.f)? h2 : 0.2f*h2;
      float h3 = acc[i][3]+bb3; h3 = (h3>0.f)? h3 : 0.2f*h3;
      float* hp = &Hs[(r0+i)*64 + c0];
      hp[0]=h0; hp[1]=h1; hp[2]=h2; hp[3]=h3;
    }
  }
  __syncthreads();

  // -------- stage 2: OUT = tanh(H @ W2 + b2) [ -> tanh(n2 * .) ] --------
  float a2[8][8];
  #pragma unroll
  for (int i=0;i<8;i++){
    #pragma unroll
    for (int j=0;j<8;j++) a2[i][j]=0.f;
  }
  #pragma unroll 4
  for (int k=0;k<64;k++){
    float4 w0  = *(float4*)&W2s[k*128 + c8];
    float4 w1v = *(float4*)&W2s[k*128 + c8 + 4];
    #pragma unroll
    for (int i=0;i<8;i++){
      float xv = Hs[(r0+i)*64 + k];
      a2[i][0]+=xv*w0.x;  a2[i][1]+=xv*w0.y;  a2[i][2]+=xv*w0.z;  a2[i][3]+=xv*w0.w;
      a2[i][4]+=xv*w1v.x; a2[i][5]+=xv*w1v.y; a2[i][6]+=xv*w1v.z; a2[i][7]+=xv*w1v.w;
    }
  }
  float c2v[8];
  #pragma unroll
  for (int j=0;j<8;j++) c2v[j] = b2[c8+j];
  #pragma unroll
  for (int i=0;i<8;i++){
    int row = row0 + r0 + i;
    float res[8];
    #pragma unroll
    for (int j=0;j<8;j++) res[j] = tanhf(a2[i][j] + c2v[j]);
    if (n2slot >= 0){
      float scv = g_s[(size_t)row*16 + n2slot];
      #pragma unroll
      for (int j=0;j<8;j++) res[j] = tanhf(scv*res[j]);
    }
    float* op = out + (size_t)row*DD + c8;
    *(float4*)op     = make_float4(res[0],res[1],res[2],res[3]);
    *(float4*)(op+4) = make_float4(res[4],res[5],res[6],res[7]);
  }
}

// ---------------- K2: gf (3 pairs) ----------------
__global__ __launch_bounds__(256) void k2_gf(
    const float* __restrict__ w1, const float* __restrict__ b1,
    const float* __restrict__ w2, const float* __restrict__ b2)
{
  const float *x1, *x2;
  int p = blockIdx.y;
  if (p==0){ x1=g_Pa; x2=g_Pv; }
  else if (p==1){ x1=g_Pa; x2=g_Pl; }
  else { x1=g_Pv; x2=g_Pl; }
  mlp2(x1,x2,w1,b1,w2,b2, g_G + (size_t)p*SLOT, blockIdx.x*128, -1);
}

// ---------------- K3: rowwise mid (warp per row) ----------------
__global__ __launch_bounds__(256) void k3_mid()
{
  int gw   = (int)((blockIdx.x*blockDim.x + threadIdx.x) >> 5);
  int lane = threadIdx.x & 31;
  size_t base = (size_t)gw*DD + lane*4;

  float4 gav = *(const float4*)(g_G + base);
  float4 gal = *(const float4*)(g_G + (size_t)SLOT + base);
  float4 gvl = *(const float4*)(g_G + 2*(size_t)SLOT + base);
  float4 pa = *(const float4*)(g_Pa + base);
  float4 pv = *(const float4*)(g_Pv + base);
  float4 pl = *(const float4*)(g_Pl + base);

  float m, inv;
  m = wmax(max4(gav));
  float4 A2 = make_float4(expf(gav.x-m),expf(gav.y-m),expf(gav.z-m),expf(gav.w-m));
  inv = 1.0f/wsum(sum4(A2)); A2.x*=inv; A2.y*=inv; A2.z*=inv; A2.w*=inv;
  m = wmax(max4(gal));
  float4 L2 = make_float4(expf(gal.x-m),expf(gal.y-m),expf(gal.z-m),expf(gal.w-m));
  inv = 1.0f/wsum(sum4(L2)); L2.x*=inv; L2.y*=inv; L2.z*=inv; L2.w*=inv;
  m = wmax(max4(gvl));
  float4 V2 = make_float4(expf(gvl.x-m),expf(gvl.y-m),expf(gvl.z-m),expf(gvl.w-m));
  inv = 1.0f/wsum(sum4(V2)); V2.x*=inv; V2.y*=inv; V2.z*=inv; V2.w*=inv;

  float d0 = wsum(dot4(A2,V2));   // a_v2 . v_l2
  float d1 = wsum(dot4(A2,L2));   // a_v2 . a_l2
  float d2 = wsum(dot4(L2,V2));   // a_l2 . v_l2
  float d3 = wsum(dot4(A2,pl));   // a_v2 . l
  float d4 = wsum(dot4(L2,pv));   // a_l2 . v
  float d5 = wsum(dot4(V2,pa));   // v_l2 . a

  const float* s = g_s + (size_t)gw*16;
  float sa1=s[0], sv1=s[1], sl1=s[2], sav=s[3], sal=s[4], svl=s[5];
  float nm0=s[6], nm1=s[7], nm2=s[8];

  float e0=(sav+svl)/(d0+0.5f);
  float e1=(sav+sal)/(d1+0.5f);
  float e2=(sal+svl)/(d2+0.5f);
  float e3=(sav+sl1)/(d3+0.5f);
  float e4=(sal+sv1)/(d4+0.5f);
  float e5=(sa1+svl)/(d5+0.5f);
  float mm = fmaxf(fmaxf(fmaxf(e0,e1),fmaxf(e2,e3)),fmaxf(e4,e5));
  float x0=expf(e0-mm),x1=expf(e1-mm),x2=expf(e2-mm);
  float x3=expf(e3-mm),x4=expf(e4-mm),x5=expf(e5-mm);
  float ri = 1.0f/(x0+x1+x2+x3+x4+x5);
  if (lane==0){
    float* sw = g_s + (size_t)gw*16;
    sw[9]=x0*ri; sw[10]=x1*ri; sw[11]=x2*ri; sw[12]=x3*ri; sw[13]=x4*ri; sw[14]=x5*ri;
  }

  float4 AV = make_float4(tanhf(nm0*gav.x),tanhf(nm0*gav.y),tanhf(nm0*gav.z),tanhf(nm0*gav.w));
  float4 AL = make_float4(tanhf(nm1*gal.x),tanhf(nm1*gal.y),tanhf(nm1*gal.z),tanhf(nm1*gal.w));
  float4 VL = make_float4(tanhf(nm2*gvl.x),tanhf(nm2*gvl.y),tanhf(nm2*gvl.z),tanhf(nm2*gvl.w));

  *(float4*)(g_G + base) = AV;
  *(float4*)(g_G + (size_t)SLOT + base) = AL;
  *(float4*)(g_G + 2*(size_t)SLOT + base) = VL;

  float4 bi = make_float4(AV.x+AL.x+VL.x, AV.y+AL.y+VL.y, AV.z+AL.z+VL.z, AV.w+AL.w+VL.w);
  *(float4*)(g_bi + base) = bi;
}

// ---------------- K4: gf2 (6 pairs, n2-scaled epilogue) ----------------
__global__ __launch_bounds__(256) void k4_gf2(
    const float* __restrict__ w1, const float* __restrict__ b1,
    const float* __restrict__ w2, const float* __restrict__ b2)
{
  const float* av = g_G;
  const float* al = g_G + (size_t)SLOT;
  const float* vl = g_G + 2*(size_t)SLOT;
  const float *x1, *x2;
  int p = blockIdx.y;
  switch(p){
    case 0: x1=av; x2=vl;   break;  // gf2(a_v, v_l)
    case 1: x1=av; x2=al;   break;  // gf2(a_v, a_l)
    case 2: x1=vl; x2=al;   break;  // gf2(v_l, a_l)
    case 3: x1=av; x2=g_Pl; break;  // gf2(a_v, l)
    case 4: x1=al; x2=g_Pv; break;  // gf2(a_l, v)
    default:x1=vl; x2=g_Pa; break;  // gf2(v_l, a)
  }
  mlp2(x1,x2,w1,b1,w2,b2, g_G2 + (size_t)p*SLOT, blockIdx.x*128, 9+p);
}

// ---------------- K5: trimodal sum ----------------
__global__ __launch_bounds__(256) void k5_tri()
{
  size_t i = ((size_t)blockIdx.x*blockDim.x + threadIdx.x)*4;
  float4 r = *(const float4*)(g_G2 + i);
  #pragma unroll
  for (int p=1;p<6;p++){
    float4 t = *(const float4*)(g_G2 + (size_t)p*SLOT + i);
    r.x+=t.x; r.y+=t.y; r.z+=t.z; r.w+=t.w;
  }
  *(float4*)(g_tri+i) = r;
}

// ---------------- K6: fused 3-layer head -> out ----------------
__global__ __launch_bounds__(256) void k6_ll(
    const float* __restrict__ w1, const float* __restrict__ b1,
    const float* __restrict__ w2, const float* __restrict__ b2,
    const float* __restrict__ w3, const float* __restrict__ b3,
    float* __restrict__ out)
{
  extern __shared__ float sm[];
  float* Xs  = sm;              // 128 x 65 = 8320
  float* H1s = sm + 8320;       // 8192
  float* H2s = sm + 16512;      // 8192
  float* W1c = sm + 24704;      // 4096
  float* W2s = sm + 28800;      // 4096
  float* W3s = sm + 32896;      // 8192 -> total 41088 floats = 164352B

  int tid = threadIdx.x;
  int row0 = blockIdx.x * 128;

  #pragma unroll
  for (int i = tid*4; i < 4096; i += 1024)
    *(float4*)&W2s[i] = *(const float4*)&w2[i];
  #pragma unroll
  for (int i = tid*4; i < 8192; i += 1024)
    *(float4*)&W3s[i] = *(const float4*)&w3[i];

  int tc = tid & 15, tr = tid >> 4;
  int r0 = tr*8, c0 = tc*4, c8 = tc*8;

  float acc[8][4];
  #pragma unroll
  for (int i=0;i<8;i++){
    #pragma unroll
    for (int j=0;j<4;j++) acc[i][j]=0.f;
  }

  // stage A: H1 = tanh([uni|bi|tri] @ W1 + b1), K=384 in 6 chunks
  #pragma unroll 1
  for (int ch=0; ch<6; ch++){
    const float* src = (ch<2) ? g_uni : (ch<4) ? g_bi : g_tri;
    int kc = (ch&1)*64;
    __syncthreads();
    #pragma unroll
    for (int it=0; it<8; it++){
      int idx = tid*4 + it*1024;
      int r = idx>>6, kk = idx&63;
      float4 t = *(const float4*)(src + (size_t)(row0+r)*DD + kc + kk);
      float* d = &Xs[r*65 + kk];
      d[0]=t.x; d[1]=t.y; d[2]=t.z; d[3]=t.w;
    }
    #pragma unroll
    for (int it=0; it<4; it++){
      int idx = tid*4 + it*1024;
      *(float4*)&W1c[idx] = *(const float4*)&w1[ch*4096 + idx];
    }
    __syncthreads();
    #pragma unroll 4
    for (int k=0;k<64;k++){
      float4 wv = *(float4*)&W1c[k*64 + c0];
      #pragma unroll
      for (int i=0;i<8;i++){
        float xv = Xs[(r0+i)*65 + k];
        acc[i][0] += xv*wv.x; acc[i][1] += xv*wv.y;
        acc[i][2] += xv*wv.z; acc[i][3] += xv*wv.w;
      }
    }
  }
  __syncthreads();
  {
    float bb0=b1[c0], bb1=b1[c0+1], bb2=b1[c0+2], bb3=b1[c0+3];
    #pragma unroll
    for (int i=0;i<8;i++){
      float* hp = &H1s[(r0+i)*64 + c0];
      hp[0]=tanhf(acc[i][0]+bb0); hp[1]=tanhf(acc[i][1]+bb1);
      hp[2]=tanhf(acc[i][2]+bb2); hp[3]=tanhf(acc[i][3]+bb3);
    }
  }
  __syncthreads();

  // stage B: H2 = tanh(H1 @ W2 + b2)
  float a2[8][4];
  #pragma unroll
  for (int i=0;i<8;i++){
    #pragma unroll
    for (int j=0;j<4;j++) a2[i][j]=0.f;
  }
  #pragma unroll 4
  for (int k=0;k<64;k++){
    float4 wv = *(float4*)&W2s[k*64 + c0];
    #pragma unroll
    for (int i=0;i<8;i++){
      float xv = H1s[(r0+i)*64 + k];
      a2[i][0]+=xv*wv.x; a2[i][1]+=xv*wv.y; a2[i][2]+=xv*wv.z; a2[i][3]+=xv*wv.w;
    }
  }
  {
    float bb0=b2[c0], bb1=b2[c0+1], bb2x=b2[c0+2], bb3=b2[c0+3];
    #pragma unroll
    for (int i=0;i<8;i++){
      float* hp = &H2s[(r0+i)*64 + c0];
      hp[0]=tanhf(a2[i][0]+bb0); hp[1]=tanhf(a2[i][1]+bb1);
      hp[2]=tanhf(a2[i][2]+bb2x); hp[3]=tanhf(a2[i][3]+bb3);
    }
  }
  __syncthreads();

  // stage C: OUT = tanh(H2 @ W3 + b3)
  float a3[8][8];
  #pragma unroll
  for (int i=0;i<8;i++){
    #pragma unroll
    for (int j=0;j<8;j++) a3[i][j]=0.f;
  }
  #pragma unroll 4
  for (int k=0;k<64;k++){
    float4 w0  = *(float4*)&W3s[k*128 + c8];
    float4 w1v = *(float4*)&W3s[k*128 + c8 + 4];
    #pragma unroll
    for (int i=0;i<8;i++){
      float xv = H2s[(r0+i)*64 + k];
      a3[i][0]+=xv*w0.x;  a3[i][1]+=xv*w0.y;  a3[i][2]+=xv*w0.z;  a3[i][3]+=xv*w0.w;
      a3[i][4]+=xv*w1v.x; a3[i][5]+=xv*w1v.y; a3[i][6]+=xv*w1v.z; a3[i][7]+=xv*w1v.w;
    }
  }
  float c3v[8];
  #pragma unroll
  for (int j=0;j<8;j++) c3v[j] = b3[c8+j];
  #pragma unroll
  for (int i=0;i<8;i++){
    int row = row0 + r0 + i;
    float res[8];
    #pragma unroll
    for (int j=0;j<8;j++) res[j] = tanhf(a3[i][j] + c3v[j]);
    float* op = out + (size_t)row*DD + c8;
    *(float4*)op     = make_float4(res[0],res[1],res[2],res[3]);
    *(float4*)(op+4) = make_float4(res[4],res[5],res[6],res[7]);
  }
}

// ---------------- launch ----------------
extern "C" void kernel_launch(void* const* d_in, const int* in_sizes, int n_in,
                              void* d_out, int out_size)
{
  (void)in_sizes; (void)n_in; (void)out_size;
  const float* L     = (const float*)d_in[0];
  const float* A     = (const float*)d_in[1];
  const float* V     = (const float*)d_in[2];
  const float* attw  = (const float*)d_in[3];
  const float* attb  = (const float*)d_in[4];
  const float* gfw1  = (const float*)d_in[5];
  const float* gfb1  = (const float*)d_in[6];
  const float* gfw2  = (const float*)d_in[7];
  const float* gfb2  = (const float*)d_in[8];
  const float* gf2w1 = (const float*)d_in[9];
  const float* gf2b1 = (const float*)d_in[10];
  const float* gf2w2 = (const float*)d_in[11];
  const float* gf2b2 = (const float*)d_in[12];
  const float* llw1  = (const float*)d_in[13];
  const float* llb1  = (const float*)d_in[14];
  const float* llw2  = (const float*)d_in[15];
  const float* llb2  = (const float*)d_in[16];
  const float* llw3  = (const float*)d_in[17];
  const float* llb3  = (const float*)d_in[18];
  float* out = (float*)d_out;

  const int SMEM2 = 28800*4;   // 115200
  const int SMEM6 = 41088*4;   // 164352
  cudaFuncSetAttribute(k2_gf,  cudaFuncAttributeMaxDynamicSharedMemorySize, SMEM2);
  cudaFuncSetAttribute(k4_gf2, cudaFuncAttributeMaxDynamicSharedMemorySize, SMEM2);
  cudaFuncSetAttribute(k6_ll,  cudaFuncAttributeMaxDynamicSharedMemorySize, SMEM6);

  k1_pre<<<NB/8, 256>>>(L, A, V, attw, attb);
  k2_gf<<<dim3(NB/128, 3), 256, SMEM2>>>(gfw1, gfb1, gfw2, gfb2);
  k3_mid<<<NB/8, 256>>>();
  k4_gf2<<<dim3(NB/128, 6), 256, SMEM2>>>(gf2w1, gf2b1, gf2w2, gf2b2);
  k5_tri<<<SLOT/1024, 256>>>();
  k6_ll<<<NB/128, 256, SMEM6>>>(llw1, llb1, llw2, llb2, llw3, llb3, out);
}

// round 5
// speedup vs baseline: 1.7592x; 1.7592x over previous
#include <cuda_runtime.h>
#include <cuda_bf16.h>
#include <cstdint>

#define NB 65536
#define DD 128
#define SLOT (NB*DD)

// ---------------- scratch ----------------
__device__ float g_Pa[SLOT];
__device__ float g_Pv[SLOT];
__device__ float g_Pl[SLOT];
__device__ float g_uni[SLOT];
__device__ float g_bi[SLOT];
__device__ float g_G[3*SLOT];
__device__ float g_G2[6*SLOT];
__device__ float g_s[NB*16];

// pre-split n-major bf16 weight images
__device__ __align__(16) unsigned short g_gfW1h[2][16384], g_gfW1l[2][16384]; // [n*256+k], n<64
__device__ __align__(16) unsigned short g_gfW2h[2][8192],  g_gfW2l[2][8192];  // [n*64+k],  n<128
__device__ __align__(16) unsigned short g_llW1h[24576],    g_llW1l[24576];    // [n*384+k], n<64
__device__ __align__(16) unsigned short g_llW2h[4096],     g_llW2l[4096];     // [n*64+k],  n<64
__device__ __align__(16) unsigned short g_llW3h[8192],     g_llW3l[8192];     // [n*64+k],  n<128

extern __shared__ char smem_raw[];

// ---------------- helpers ----------------
__device__ __forceinline__ float wsum(float x){
  #pragma unroll
  for (int o=16;o;o>>=1) x += __shfl_xor_sync(0xffffffffu, x, o);
  return x;
}
__device__ __forceinline__ float wmax(float x){
  #pragma unroll
  for (int o=16;o;o>>=1) x = fmaxf(x, __shfl_xor_sync(0xffffffffu, x, o));
  return x;
}
__device__ __forceinline__ float dot4(float4 a, float4 b){
  return a.x*b.x + a.y*b.y + a.z*b.z + a.w*b.w;
}
__device__ __forceinline__ float max4(float4 a){ return fmaxf(fmaxf(a.x,a.y),fmaxf(a.z,a.w)); }
__device__ __forceinline__ float sum4(float4 a){ return a.x+a.y+a.z+a.w; }

__device__ __forceinline__ void split_pack2(float x, float y, uint32_t &h, uint32_t &l){
  __nv_bfloat16 hx = __float2bfloat16(x);
  __nv_bfloat16 hy = __float2bfloat16(y);
  float rx = x - __bfloat162float(hx);
  float ry = y - __bfloat162float(hy);
  __nv_bfloat16 lx = __float2bfloat16(rx);
  __nv_bfloat16 ly = __float2bfloat16(ry);
  h = (uint32_t)__bfloat16_as_ushort(hx) | ((uint32_t)__bfloat16_as_ushort(hy) << 16);
  l = (uint32_t)__bfloat16_as_ushort(lx) | ((uint32_t)__bfloat16_as_ushort(ly) << 16);
}
__device__ __forceinline__ void split_one(float x, unsigned short &h, unsigned short &l){
  __nv_bfloat16 hx = __float2bfloat16(x);
  float rx = x - __bfloat162float(hx);
  __nv_bfloat16 lx = __float2bfloat16(rx);
  h = __bfloat16_as_ushort(hx);
  l = __bfloat16_as_ushort(lx);
}

#define MMA(c, a, bb0, bb1) \
  asm volatile("mma.sync.aligned.m16n8k16.row.col.f32.bf16.bf16.f32 " \
    "{%0,%1,%2,%3}, {%4,%5,%6,%7}, {%8,%9}, {%0,%1,%2,%3};" \
    : "+f"((c)[0]),"+f"((c)[1]),"+f"((c)[2]),"+f"((c)[3]) \
    : "r"((a)[0]),"r"((a)[1]),"r"((a)[2]),"r"((a)[3]), "r"(bb0),"r"(bb1))

__device__ __forceinline__ float lrelu(float x){ return (x > 0.f) ? x : 0.2f*x; }

// ---------------- K0: weight split to n-major bf16 hi/lo ----------------
__global__ __launch_bounds__(256) void k0_conv(
    const float* __restrict__ gw1,  const float* __restrict__ gw2,
    const float* __restrict__ g2w1, const float* __restrict__ g2w2,
    const float* __restrict__ lw1,  const float* __restrict__ lw2,
    const float* __restrict__ lw3)
{
  int y = blockIdx.y;
  int e = blockIdx.x*256 + threadIdx.x;
  if (y < 2){
    const float* w1 = y ? g2w1 : gw1;  // [256,64]
    const float* w2 = y ? g2w2 : gw2;  // [64,128]
    if (e < 16384){
      int k = e >> 6, n = e & 63;
      unsigned short h,l; split_one(w1[e], h, l);
      g_gfW1h[y][n*256+k] = h; g_gfW1l[y][n*256+k] = l;
    } else if (e < 24576){
      int e2 = e - 16384;
      int k = e2 >> 7, n = e2 & 127;
      unsigned short h,l; split_one(w2[e2], h, l);
      g_gfW2h[y][n*64+k] = h; g_gfW2l[y][n*64+k] = l;
    }
  } else {
    if (e < 24576){               // ll_w1 [384,64]
      int k = e >> 6, n = e & 63;
      unsigned short h,l; split_one(lw1[e], h, l);
      g_llW1h[n*384+k] = h; g_llW1l[n*384+k] = l;
    } else if (e < 28672){        // ll_w2 [64,64]
      int e2 = e - 24576;
      int k = e2 >> 6, n = e2 & 63;
      unsigned short h,l; split_one(lw2[e2], h, l);
      g_llW2h[n*64+k] = h; g_llW2l[n*64+k] = l;
    } else if (e < 36864){        // ll_w3 [64,128]
      int e2 = e - 28672;
      int k = e2 >> 7, n = e2 & 127;
      unsigned short h,l; split_one(lw3[e2], h, l);
      g_llW3h[n*64+k] = h; g_llW3l[n*64+k] = l;
    }
  }
}

// ---------------- K1: rowwise pre ----------------
__global__ __launch_bounds__(256) void k1_pre(
    const float* __restrict__ L, const float* __restrict__ A,
    const float* __restrict__ V, const float* __restrict__ attw,
    const float* __restrict__ attb)
{
  int gw   = (int)((blockIdx.x*blockDim.x + threadIdx.x) >> 5);
  int lane = threadIdx.x & 31;
  size_t base = (size_t)gw*DD + lane*4;

  float4 av = *(const float4*)(A+base);
  float4 vv = *(const float4*)(V+base);
  float4 lv = *(const float4*)(L+base);
  float4 wv = *(const float4*)(attw + lane*4);
  float bb = attb[0];

  float sa = tanhf(wsum(dot4(av,wv)) + bb);
  float sv = tanhf(wsum(dot4(vv,wv)) + bb);
  float sl = tanhf(wsum(dot4(lv,wv)) + bb);

  float4 u;
  u.x = (sa*av.x + sv*vv.x + sl*lv.x)*(1.0f/3.0f);
  u.y = (sa*av.y + sv*vv.y + sl*lv.y)*(1.0f/3.0f);
  u.z = (sa*av.z + sv*vv.z + sl*lv.z)*(1.0f/3.0f);
  u.w = (sa*av.w + sv*vv.w + sl*lv.w)*(1.0f/3.0f);
  *(float4*)(g_uni+base) = u;

  float m = wmax(max4(av));
  float4 pa = make_float4(expf(av.x-m),expf(av.y-m),expf(av.z-m),expf(av.w-m));
  float inv = 1.0f/wsum(sum4(pa));
  pa.x*=inv; pa.y*=inv; pa.z*=inv; pa.w*=inv;
  m = wmax(max4(vv));
  float4 pv = make_float4(expf(vv.x-m),expf(vv.y-m),expf(vv.z-m),expf(vv.w-m));
  inv = 1.0f/wsum(sum4(pv));
  pv.x*=inv; pv.y*=inv; pv.z*=inv; pv.w*=inv;
  m = wmax(max4(lv));
  float4 pl = make_float4(expf(lv.x-m),expf(lv.y-m),expf(lv.z-m),expf(lv.w-m));
  inv = 1.0f/wsum(sum4(pl));
  pl.x*=inv; pl.y*=inv; pl.z*=inv; pl.w*=inv;

  *(float4*)(g_Pa+base) = pa;
  *(float4*)(g_Pv+base) = pv;
  *(float4*)(g_Pl+base) = pl;

  float dav = wsum(dot4(pa,pv));
  float dal = wsum(dot4(pa,pl));
  float dvl = wsum(dot4(pv,pl));

  float sav = (sa+sv)/(dav+0.5f);
  float sal = (sa+sl)/(dal+0.5f);
  float svl = (sl+sv)/(dvl+0.5f);

  float m3 = fmaxf(sav,fmaxf(sal,svl));
  float e0 = expf(sav-m3), e1 = expf(sal-m3), e2 = expf(svl-m3);
  float r3 = 1.0f/(e0+e1+e2);

  if (lane==0){
    float* s = g_s + (size_t)gw*16;
    s[0]=sa; s[1]=sv; s[2]=sl;
    s[3]=sav; s[4]=sal; s[5]=svl;
    s[6]=e0*r3; s[7]=e1*r3; s[8]=e2*r3;
  }
}

// ---------------- fused 2-layer MLP via mma.sync bf16x3 ----------------
// smem: [0] b1s 64f | [256] b2s 128f | [768] W1h 64x264 | +33792 W1l
//       [68352] W2h 128x72 | +18432 W2l   -> 105216 B
#define SMEM_MLP 105216

__device__ __forceinline__ void mlp2_mma(
    const float* __restrict__ x1, const float* __restrict__ x2,
    const float* __restrict__ b1, const float* __restrict__ b2,
    const unsigned short* __restrict__ w1h_g, const unsigned short* __restrict__ w1l_g,
    const unsigned short* __restrict__ w2h_g, const unsigned short* __restrict__ w2l_g,
    float* __restrict__ out, int row0, int n2slot)
{
  float* b1s = (float*)(smem_raw);
  float* b2s = (float*)(smem_raw + 256);
  unsigned short* W1h = (unsigned short*)(smem_raw + 768);
  unsigned short* W1l = W1h + 16896;
  unsigned short* W2h = W1l + 16896;
  unsigned short* W2l = W2h + 9216;

  int tid = threadIdx.x;

  // stage weights into smem (padded strides: W1 264, W2 72)
  #pragma unroll
  for (int idx = tid; idx < 2048; idx += 256){
    int row = idx >> 5, j = idx & 31;
    *((uint4*)(W1h + row*264) + j) = ((const uint4*)w1h_g)[idx];
    *((uint4*)(W1l + row*264) + j) = ((const uint4*)w1l_g)[idx];
  }
  #pragma unroll
  for (int idx = tid; idx < 1024; idx += 256){
    int row = idx >> 3, j = idx & 7;
    *((uint4*)(W2h + row*72) + j) = ((const uint4*)w2h_g)[idx];
    *((uint4*)(W2l + row*72) + j) = ((const uint4*)w2l_g)[idx];
  }
  if (tid < 64)  b1s[tid] = b1[tid];
  if (tid < 128) b2s[tid] = b2[tid];
  __syncthreads();

  int w = tid >> 5, lane = tid & 31;
  int g = lane >> 2, tg = lane & 3;
  int r0 = row0 + w*16 + g;
  int r1 = r0 + 8;

  // -------- stage 1: concat(x1,x2)[128x256] @ W1[256x64] --------
  float acc[8][4];
  #pragma unroll
  for (int i=0;i<8;i++){ acc[i][0]=0.f; acc[i][1]=0.f; acc[i][2]=0.f; acc[i][3]=0.f; }

  #pragma unroll 1
  for (int kk = 0; kk < 16; kk++){
    const float* sp = (kk < 8) ? x1 : x2;
    int cc = (kk & 7)*16 + tg*2;
    const float* p0 = sp + (size_t)r0*DD + cc;
    const float* p1 = sp + (size_t)r1*DD + cc;
    float2 v00 = *(const float2*)p0;
    float2 v01 = *(const float2*)(p0 + 8);
    float2 v10 = *(const float2*)p1;
    float2 v11 = *(const float2*)(p1 + 8);
    uint32_t ah[4], al[4];
    split_pack2(v00.x, v00.y, ah[0], al[0]);
    split_pack2(v10.x, v10.y, ah[1], al[1]);
    split_pack2(v01.x, v01.y, ah[2], al[2]);
    split_pack2(v11.x, v11.y, ah[3], al[3]);
    int kb = kk*16 + tg*2;
    #pragma unroll
    for (int nt = 0; nt < 8; nt++){
      const unsigned short* bp = W1h + (nt*8+g)*264 + kb;
      const unsigned short* bq = W1l + (nt*8+g)*264 + kb;
      uint32_t bh0 = *(const uint32_t*)bp;
      uint32_t bh1 = *(const uint32_t*)(bp + 8);
      uint32_t bl0 = *(const uint32_t*)bq;
      uint32_t bl1 = *(const uint32_t*)(bq + 8);
      MMA(acc[nt], ah, bh0, bh1);
      MMA(acc[nt], ah, bl0, bl1);
      MMA(acc[nt], al, bh0, bh1);
    }
  }

  // -------- H = lrelu(acc + b1) -> A-fragments (in registers) --------
  uint32_t hh[4][4], hl[4][4];
  #pragma unroll
  for (int kt = 0; kt < 4; kt++){
    float* t0 = acc[2*kt];
    float* t1 = acc[2*kt+1];
    int c0 = kt*16 + tg*2;
    float bA = b1s[c0], bB = b1s[c0+1], bC = b1s[c0+8], bD = b1s[c0+9];
    float h00 = lrelu(t0[0]+bA), h01 = lrelu(t0[1]+bB);
    float h10 = lrelu(t0[2]+bA), h11 = lrelu(t0[3]+bB);
    float h20 = lrelu(t1[0]+bC), h21 = lrelu(t1[1]+bD);
    float h30 = lrelu(t1[2]+bC), h31 = lrelu(t1[3]+bD);
    split_pack2(h00, h01, hh[kt][0], hl[kt][0]);
    split_pack2(h10, h11, hh[kt][1], hl[kt][1]);
    split_pack2(h20, h21, hh[kt][2], hl[kt][2]);
    split_pack2(h30, h31, hh[kt][3], hl[kt][3]);
  }

  // -------- stage 2: H[128x64] @ W2[64x128], in two N-halves --------
  float scv0 = 0.f, scv1 = 0.f;
  if (n2slot >= 0){
    scv0 = g_s[(size_t)r0*16 + n2slot];
    scv1 = g_s[(size_t)r1*16 + n2slot];
  }
  #pragma unroll 1
  for (int nh = 0; nh < 2; nh++){
    float acc2[8][4];
    #pragma unroll
    for (int i=0;i<8;i++){ acc2[i][0]=0.f; acc2[i][1]=0.f; acc2[i][2]=0.f; acc2[i][3]=0.f; }
    #pragma unroll
    for (int nt = 0; nt < 8; nt++){
      int n = (nh*8+nt)*8 + g;
      #pragma unroll
      for (int kt = 0; kt < 4; kt++){
        const unsigned short* bp = W2h + n*72 + kt*16 + tg*2;
        const unsigned short* bq = W2l + n*72 + kt*16 + tg*2;
        uint32_t bh0 = *(const uint32_t*)bp;
        uint32_t bh1 = *(const uint32_t*)(bp + 8);
        uint32_t bl0 = *(const uint32_t*)bq;
        uint32_t bl1 = *(const uint32_t*)(bq + 8);
        MMA(acc2[nt], hh[kt], bh0, bh1);
        MMA(acc2[nt], hh[kt], bl0, bl1);
        MMA(acc2[nt], hl[kt], bh0, bh1);
      }
    }
    #pragma unroll
    for (int nt = 0; nt < 8; nt++){
      int col = (nh*8+nt)*8 + tg*2;
      float v0 = tanhf(acc2[nt][0] + b2s[col]);
      float v1 = tanhf(acc2[nt][1] + b2s[col+1]);
      float v2 = tanhf(acc2[nt][2] + b2s[col]);
      float v3 = tanhf(acc2[nt][3] + b2s[col+1]);
      if (n2slot >= 0){
        v0 = tanhf(scv0*v0); v1 = tanhf(scv0*v1);
        v2 = tanhf(scv1*v2); v3 = tanhf(scv1*v3);
      }
      *(float2*)(out + (size_t)r0*DD + col) = make_float2(v0, v1);
      *(float2*)(out + (size_t)r1*DD + col) = make_float2(v2, v3);
    }
  }
}

__global__ __launch_bounds__(256) void k2_tc(const float* __restrict__ b1, const float* __restrict__ b2)
{
  const float *x1, *x2;
  int p = blockIdx.y;
  if (p==0){ x1=g_Pa; x2=g_Pv; }
  else if (p==1){ x1=g_Pa; x2=g_Pl; }
  else { x1=g_Pv; x2=g_Pl; }
  mlp2_mma(x1, x2, b1, b2, g_gfW1h[0], g_gfW1l[0], g_gfW2h[0], g_gfW2l[0],
           g_G + (size_t)p*SLOT, blockIdx.x*128, -1);
}

__global__ __launch_bounds__(256) void k4_tc(const float* __restrict__ b1, const float* __restrict__ b2)
{
  const float* av = g_G;
  const float* al = g_G + (size_t)SLOT;
  const float* vl = g_G + 2*(size_t)SLOT;
  const float *x1, *x2;
  int p = blockIdx.y;
  switch(p){
    case 0: x1=av; x2=vl;   break;
    case 1: x1=av; x2=al;   break;
    case 2: x1=vl; x2=al;   break;
    case 3: x1=av; x2=g_Pl; break;
    case 4: x1=al; x2=g_Pv; break;
    default:x1=vl; x2=g_Pa; break;
  }
  mlp2_mma(x1, x2, b1, b2, g_gfW1h[1], g_gfW1l[1], g_gfW2h[1], g_gfW2l[1],
           g_G2 + (size_t)p*SLOT, blockIdx.x*128, 9+p);
}

// ---------------- K3: rowwise mid ----------------
__global__ __launch_bounds__(256) void k3_mid()
{
  int gw   = (int)((blockIdx.x*blockDim.x + threadIdx.x) >> 5);
  int lane = threadIdx.x & 31;
  size_t base = (size_t)gw*DD + lane*4;

  float4 gav = *(const float4*)(g_G + base);
  float4 gal = *(const float4*)(g_G + (size_t)SLOT + base);
  float4 gvl = *(const float4*)(g_G + 2*(size_t)SLOT + base);
  float4 pa = *(const float4*)(g_Pa + base);
  float4 pv = *(const float4*)(g_Pv + base);
  float4 pl = *(const float4*)(g_Pl + base);

  float m, inv;
  m = wmax(max4(gav));
  float4 A2 = make_float4(expf(gav.x-m),expf(gav.y-m),expf(gav.z-m),expf(gav.w-m));
  inv = 1.0f/wsum(sum4(A2)); A2.x*=inv; A2.y*=inv; A2.z*=inv; A2.w*=inv;
  m = wmax(max4(gal));
  float4 L2 = make_float4(expf(gal.x-m),expf(gal.y-m),expf(gal.z-m),expf(gal.w-m));
  inv = 1.0f/wsum(sum4(L2)); L2.x*=inv; L2.y*=inv; L2.z*=inv; L2.w*=inv;
  m = wmax(max4(gvl));
  float4 V2 = make_float4(expf(gvl.x-m),expf(gvl.y-m),expf(gvl.z-m),expf(gvl.w-m));
  inv = 1.0f/wsum(sum4(V2)); V2.x*=inv; V2.y*=inv; V2.z*=inv; V2.w*=inv;

  float d0 = wsum(dot4(A2,V2));
  float d1 = wsum(dot4(A2,L2));
  float d2 = wsum(dot4(L2,V2));
  float d3 = wsum(dot4(A2,pl));
  float d4 = wsum(dot4(L2,pv));
  float d5 = wsum(dot4(V2,pa));

  const float* s = g_s + (size_t)gw*16;
  float sa1=s[0], sv1=s[1], sl1=s[2], sav=s[3], sal=s[4], svl=s[5];
  float nm0=s[6], nm1=s[7], nm2=s[8];

  float e0=(sav+svl)/(d0+0.5f);
  float e1=(sav+sal)/(d1+0.5f);
  float e2=(sal+svl)/(d2+0.5f);
  float e3=(sav+sl1)/(d3+0.5f);
  float e4=(sal+sv1)/(d4+0.5f);
  float e5=(sa1+svl)/(d5+0.5f);
  float mm = fmaxf(fmaxf(fmaxf(e0,e1),fmaxf(e2,e3)),fmaxf(e4,e5));
  float x0=expf(e0-mm),x1=expf(e1-mm),x2=expf(e2-mm);
  float x3=expf(e3-mm),x4=expf(e4-mm),x5=expf(e5-mm);
  float ri = 1.0f/(x0+x1+x2+x3+x4+x5);
  if (lane==0){
    float* sw = g_s + (size_t)gw*16;
    sw[9]=x0*ri; sw[10]=x1*ri; sw[11]=x2*ri; sw[12]=x3*ri; sw[13]=x4*ri; sw[14]=x5*ri;
  }

  float4 AV = make_float4(tanhf(nm0*gav.x),tanhf(nm0*gav.y),tanhf(nm0*gav.z),tanhf(nm0*gav.w));
  float4 AL = make_float4(tanhf(nm1*gal.x),tanhf(nm1*gal.y),tanhf(nm1*gal.z),tanhf(nm1*gal.w));
  float4 VL = make_float4(tanhf(nm2*gvl.x),tanhf(nm2*gvl.y),tanhf(nm2*gvl.z),tanhf(nm2*gvl.w));

  *(float4*)(g_G + base) = AV;
  *(float4*)(g_G + (size_t)SLOT + base) = AL;
  *(float4*)(g_G + 2*(size_t)SLOT + base) = VL;

  float4 bi = make_float4(AV.x+AL.x+VL.x, AV.y+AL.y+VL.y, AV.z+AL.z+VL.z, AV.w+AL.w+VL.w);
  *(float4*)(g_bi + base) = bi;
}

// ---------------- K6: fused 3-layer head via mma (tri summed inline) ----------------
// smem: [0] b1s 64f | [256] b2s 64f | [512] b3s 128f |
//  [1024] W1h 64x392 (50176B) | [51200] W1l | [101376] W2h 64x72 (9216B) | [110592] W2l |
//  [119808] W3h 128x72 (18432B) | [138240] W3l  -> 156672 B
#define SMEM_K6 156672

__global__ __launch_bounds__(256) void k6_tc(
    const float* __restrict__ b1, const float* __restrict__ b2,
    const float* __restrict__ b3, float* __restrict__ out)
{
  float* b1s = (float*)(smem_raw);
  float* b2s = (float*)(smem_raw + 256);
  float* b3s = (float*)(smem_raw + 512);
  unsigned short* W1h = (unsigned short*)(smem_raw + 1024);
  unsigned short* W1l = W1h + 25088;   // 64*392
  unsigned short* W2h = W1l + 25088;
  unsigned short* W2l = W2h + 4608;    // 64*72
  unsigned short* W3h = W2l + 4608;
  unsigned short* W3l = W3h + 9216;    // 128*72

  int tid = threadIdx.x;
  int row0 = blockIdx.x * 128;

  // stage weights (W1: 64 rows x 384 = 48 uint4/row -> stride 392; W2/W3: 8 uint4/row -> stride 72)
  #pragma unroll
  for (int idx = tid; idx < 3072; idx += 256){
    int row = idx / 48, j = idx % 48;
    *((uint4*)(W1h + row*392) + j) = ((const uint4*)g_llW1h)[idx];
    *((uint4*)(W1l + row*392) + j) = ((const uint4*)g_llW1l)[idx];
  }
  #pragma unroll
  for (int idx = tid; idx < 512; idx += 256){
    int row = idx >> 3, j = idx & 7;
    *((uint4*)(W2h + row*72) + j) = ((const uint4*)g_llW2h)[idx];
    *((uint4*)(W2l + row*72) + j) = ((const uint4*)g_llW2l)[idx];
  }
  #pragma unroll
  for (int idx = tid; idx < 1024; idx += 256){
    int row = idx >> 3, j = idx & 7;
    *((uint4*)(W3h + row*72) + j) = ((const uint4*)g_llW3h)[idx];
    *((uint4*)(W3l + row*72) + j) = ((const uint4*)g_llW3l)[idx];
  }
  if (tid < 64)  b1s[tid] = b1[tid];
  if (tid < 64)  b2s[tid] = b2[tid];
  if (tid < 128) b3s[tid] = b3[tid];
  __syncthreads();

  int w = tid >> 5, lane = tid & 31;
  int g = lane >> 2, tg = lane & 3;
  int r0 = row0 + w*16 + g;
  int r1 = r0 + 8;

  // -------- layer 1: fusion[128x384] @ W1[384x64] --------
  float acc[8][4];
  #pragma unroll
  for (int i=0;i<8;i++){ acc[i][0]=0.f; acc[i][1]=0.f; acc[i][2]=0.f; acc[i][3]=0.f; }

  #pragma unroll 1
  for (int kk = 0; kk < 24; kk++){
    int ch = kk >> 3;
    int cc = (kk & 7)*16 + tg*2;
    size_t o0 = (size_t)r0*DD + cc;
    size_t o1 = (size_t)r1*DD + cc;
    float2 v00, v01, v10, v11;
    if (ch == 0){
      v00 = *(const float2*)(g_uni + o0); v01 = *(const float2*)(g_uni + o0 + 8);
      v10 = *(const float2*)(g_uni + o1); v11 = *(const float2*)(g_uni + o1 + 8);
    } else if (ch == 1){
      v00 = *(const float2*)(g_bi + o0); v01 = *(const float2*)(g_bi + o0 + 8);
      v10 = *(const float2*)(g_bi + o1); v11 = *(const float2*)(g_bi + o1 + 8);
    } else {
      v00 = *(const float2*)(g_G2 + o0); v01 = *(const float2*)(g_G2 + o0 + 8);
      v10 = *(const float2*)(g_G2 + o1); v11 = *(const float2*)(g_G2 + o1 + 8);
      #pragma unroll
      for (int p = 1; p < 6; p++){
        size_t po = (size_t)p*SLOT;
        float2 q;
        q = *(const float2*)(g_G2 + po + o0);     v00.x+=q.x; v00.y+=q.y;
        q = *(const float2*)(g_G2 + po + o0 + 8); v01.x+=q.x; v01.y+=q.y;
        q = *(const float2*)(g_G2 + po + o1);     v10.x+=q.x; v10.y+=q.y;
        q = *(const float2*)(g_G2 + po + o1 + 8); v11.x+=q.x; v11.y+=q.y;
      }
    }
    uint32_t ah[4], al[4];
    split_pack2(v00.x, v00.y, ah[0], al[0]);
    split_pack2(v10.x, v10.y, ah[1], al[1]);
    split_pack2(v01.x, v01.y, ah[2], al[2]);
    split_pack2(v11.x, v11.y, ah[3], al[3]);
    int kb = kk*16 + tg*2;
    #pragma unroll
    for (int nt = 0; nt < 8; nt++){
      const unsigned short* bp = W1h + (nt*8+g)*392 + kb;
      const unsigned short* bq = W1l + (nt*8+g)*392 + kb;
      uint32_t bh0 = *(const uint32_t*)bp;
      uint32_t bh1 = *(const uint32_t*)(bp + 8);
      uint32_t bl0 = *(const uint32_t*)bq;
      uint32_t bl1 = *(const uint32_t*)(bq + 8);
      MMA(acc[nt], ah, bh0, bh1);
      MMA(acc[nt], ah, bl0, bl1);
      MMA(acc[nt], al, bh0, bh1);
    }
  }

  // tanh -> H1 frags
  uint32_t hh[4][4], hl[4][4];
  #pragma unroll
  for (int kt = 0; kt < 4; kt++){
    float* t0 = acc[2*kt];
    float* t1 = acc[2*kt+1];
    int c0 = kt*16 + tg*2;
    float bA = b1s[c0], bB = b1s[c0+1], bC = b1s[c0+8], bD = b1s[c0+9];
    split_pack2(tanhf(t0[0]+bA), tanhf(t0[1]+bB), hh[kt][0], hl[kt][0]);
    split_pack2(tanhf(t0[2]+bA), tanhf(t0[3]+bB), hh[kt][1], hl[kt][1]);
    split_pack2(tanhf(t1[0]+bC), tanhf(t1[1]+bD), hh[kt][2], hl[kt][2]);
    split_pack2(tanhf(t1[2]+bC), tanhf(t1[3]+bD), hh[kt][3], hl[kt][3]);
  }

  // -------- layer 2: H1[128x64] @ W2[64x64] --------
  #pragma unroll
  for (int i=0;i<8;i++){ acc[i][0]=0.f; acc[i][1]=0.f; acc[i][2]=0.f; acc[i][3]=0.f; }
  #pragma unroll
  for (int nt = 0; nt < 8; nt++){
    int n = nt*8 + g;
    #pragma unroll
    for (int kt = 0; kt < 4; kt++){
      const unsigned short* bp = W2h + n*72 + kt*16 + tg*2;
      const unsigned short* bq = W2l + n*72 + kt*16 + tg*2;
      uint32_t bh0 = *(const uint32_t*)bp;
      uint32_t bh1 = *(const uint32_t*)(bp + 8);
      uint32_t bl0 = *(const uint32_t*)bq;
      uint32_t bl1 = *(const uint32_t*)(bq + 8);
      MMA(acc[nt], hh[kt], bh0, bh1);
      MMA(acc[nt], hh[kt], bl0, bl1);
      MMA(acc[nt], hl[kt], bh0, bh1);
    }
  }
  #pragma unroll
  for (int kt = 0; kt < 4; kt++){
    float* t0 = acc[2*kt];
    float* t1 = acc[2*kt+1];
    int c0 = kt*16 + tg*2;
    float bA = b2s[c0], bB = b2s[c0+1], bC = b2s[c0+8], bD = b2s[c0+9];
    split_pack2(tanhf(t0[0]+bA), tanhf(t0[1]+bB), hh[kt][0], hl[kt][0]);
    split_pack2(tanhf(t0[2]+bA), tanhf(t0[3]+bB), hh[kt][1], hl[kt][1]);
    split_pack2(tanhf(t1[0]+bC), tanhf(t1[1]+bD), hh[kt][2], hl[kt][2]);
    split_pack2(tanhf(t1[2]+bC), tanhf(t1[3]+bD), hh[kt][3], hl[kt][3]);
  }

  // -------- layer 3: H2[128x64] @ W3[64x128], two N-halves --------
  #pragma unroll 1
  for (int nh = 0; nh < 2; nh++){
    float acc2[8][4];
    #pragma unroll
    for (int i=0;i<8;i++){ acc2[i][0]=0.f; acc2[i][1]=0.f; acc2[i][2]=0.f; acc2[i][3]=0.f; }
    #pragma unroll
    for (int nt = 0; nt < 8; nt++){
      int n = (nh*8+nt)*8 + g;
      #pragma unroll
      for (int kt = 0; kt < 4; kt++){
        const unsigned short* bp = W3h + n*72 + kt*16 + tg*2;
        const unsigned short* bq = W3l + n*72 + kt*16 + tg*2;
        uint32_t bh0 = *(const uint32_t*)bp;
        uint32_t bh1 = *(const uint32_t*)(bp + 8);
        uint32_t bl0 = *(const uint32_t*)bq;
        uint32_t bl1 = *(const uint32_t*)(bq + 8);
        MMA(acc2[nt], hh[kt], bh0, bh1);
        MMA(acc2[nt], hh[kt], bl0, bl1);
        MMA(acc2[nt], hl[kt], bh0, bh1);
      }
    }
    #pragma unroll
    for (int nt = 0; nt < 8; nt++){
      int col = (nh*8+nt)*8 + tg*2;
      float v0 = tanhf(acc2[nt][0] + b3s[col]);
      float v1 = tanhf(acc2[nt][1] + b3s[col+1]);
      float v2 = tanhf(acc2[nt][2] + b3s[col]);
      float v3 = tanhf(acc2[nt][3] + b3s[col+1]);
      *(float2*)(out + (size_t)r0*DD + col) = make_float2(v0, v1);
      *(float2*)(out + (size_t)r1*DD + col) = make_float2(v2, v3);
    }
  }
}

// ---------------- launch ----------------
extern "C" void kernel_launch(void* const* d_in, const int* in_sizes, int n_in,
                              void* d_out, int out_size)
{
  (void)in_sizes; (void)n_in; (void)out_size;
  const float* L     = (const float*)d_in[0];
  const float* A     = (const float*)d_in[1];
  const float* V     = (const float*)d_in[2];
  const float* attw  = (const float*)d_in[3];
  const float* attb  = (const float*)d_in[4];
  const float* gfw1  = (const float*)d_in[5];
  const float* gfb1  = (const float*)d_in[6];
  const float* gfw2  = (const float*)d_in[7];
  const float* gfb2  = (const float*)d_in[8];
  const float* gf2w1 = (const float*)d_in[9];
  const float* gf2b1 = (const float*)d_in[10];
  const float* gf2w2 = (const float*)d_in[11];
  const float* gf2b2 = (const float*)d_in[12];
  const float* llw1  = (const float*)d_in[13];
  const float* llb1  = (const float*)d_in[14];
  const float* llw2  = (const float*)d_in[15];
  const float* llb2  = (const float*)d_in[16];
  const float* llw3  = (const float*)d_in[17];
  const float* llb3  = (const float*)d_in[18];
  float* out = (float*)d_out;

  cudaFuncSetAttribute(k2_tc, cudaFuncAttributeMaxDynamicSharedMemorySize, SMEM_MLP);
  cudaFuncSetAttribute(k4_tc, cudaFuncAttributeMaxDynamicSharedMemorySize, SMEM_MLP);
  cudaFuncSetAttribute(k6_tc, cudaFuncAttributeMaxDynamicSharedMemorySize, SMEM_K6);

  k0_conv<<<dim3(144,3), 256>>>(gfw1, gfw2, gf2w1, gf2w2, llw1, llw2, llw3);
  k1_pre<<<NB/8, 256>>>(L, A, V, attw, attb);
  k2_tc<<<dim3(NB/128, 3), 256, SMEM_MLP>>>(gfb1, gfb2);
  k3_mid<<<NB/8, 256>>>();
  k4_tc<<<dim3(NB/128, 6), 256, SMEM_MLP>>>(gf2b1, gf2b2);
  k6_tc<<<NB/128, 256, SMEM_K6>>>(llb1, llb2, llb3, out);
}

// round 6
// speedup vs baseline: 1.8130x; 1.0306x over previous
#include <cuda_runtime.h>
#include <cuda_bf16.h>
#include <cstdint>

#define NB 65536
#define DD 128
#define SLOT (NB*DD)
#define PSLOT (NB*64)   // uint2 pair-plane elements

// ---------------- scratch ----------------
// split pair-planes: uint2{ hi_pack(bf16 c0,c1), lo_pack(bf16 c0,c1) } per col-pair
__device__ uint2 g_sPa[PSLOT];
__device__ uint2 g_sPv[PSLOT];
__device__ uint2 g_sPl[PSLOT];
__device__ uint2 g_sUni[PSLOT];
__device__ uint2 g_sBi[PSLOT];
__device__ uint2 g_sAV[PSLOT];
__device__ uint2 g_sAL[PSLOT];
__device__ uint2 g_sVL[PSLOT];
__device__ float g_G[3*SLOT];    // gav/gal/gvl fp32 (k2 -> k3)
__device__ float g_G2[6*SLOT];   // gf2 outputs fp32 (k4 -> k6)
__device__ float g_s[NB*16];

// pre-split n-major bf16 weight images
__device__ __align__(16) unsigned short g_gfW1h[2][16384], g_gfW1l[2][16384];
__device__ __align__(16) unsigned short g_gfW2h[2][8192],  g_gfW2l[2][8192];
__device__ __align__(16) unsigned short g_llW1h[24576],    g_llW1l[24576];
__device__ __align__(16) unsigned short g_llW2h[4096],     g_llW2l[4096];
__device__ __align__(16) unsigned short g_llW3h[8192],     g_llW3l[8192];

extern __shared__ char smem_raw[];

// ---------------- helpers ----------------
__device__ __forceinline__ float wsum(float x){
  #pragma unroll
  for (int o=16;o;o>>=1) x += __shfl_xor_sync(0xffffffffu, x, o);
  return x;
}
__device__ __forceinline__ float wmax(float x){
  #pragma unroll
  for (int o=16;o;o>>=1) x = fmaxf(x, __shfl_xor_sync(0xffffffffu, x, o));
  return x;
}
__device__ __forceinline__ float dot4(float4 a, float4 b){
  return a.x*b.x + a.y*b.y + a.z*b.z + a.w*b.w;
}
__device__ __forceinline__ float max4(float4 a){ return fmaxf(fmaxf(a.x,a.y),fmaxf(a.z,a.w)); }
__device__ __forceinline__ float sum4(float4 a){ return a.x+a.y+a.z+a.w; }

__device__ __forceinline__ float fast_exp(float x){
  float e; asm("ex2.approx.f32 %0, %1;" : "=f"(e) : "f"(x*1.4426950408889634f));
  return e;
}
__device__ __forceinline__ float fast_tanh(float x){
  float e; asm("ex2.approx.f32 %0, %1;" : "=f"(e) : "f"(x*2.8853900817779268f));
  float r; asm("rcp.approx.f32 %0, %1;" : "=f"(r) : "f"(e+1.0f));
  return fmaf(-2.0f, r, 1.0f);
}

__device__ __forceinline__ void split_pack2(float x, float y, uint32_t &h, uint32_t &l){
  __nv_bfloat16 hx = __float2bfloat16(x);
  __nv_bfloat16 hy = __float2bfloat16(y);
  float rx = x - __bfloat162float(hx);
  float ry = y - __bfloat162float(hy);
  __nv_bfloat16 lx = __float2bfloat16(rx);
  __nv_bfloat16 ly = __float2bfloat16(ry);
  h = (uint32_t)__bfloat16_as_ushort(hx) | ((uint32_t)__bfloat16_as_ushort(hy) << 16);
  l = (uint32_t)__bfloat16_as_ushort(lx) | ((uint32_t)__bfloat16_as_ushort(ly) << 16);
}
__device__ __forceinline__ uint2 split_u2(float x, float y){
  uint32_t h, l; split_pack2(x, y, h, l); return make_uint2(h, l);
}
__device__ __forceinline__ void split_one(float x, unsigned short &h, unsigned short &l){
  __nv_bfloat16 hx = __float2bfloat16(x);
  float rx = x - __bfloat162float(hx);
  __nv_bfloat16 lx = __float2bfloat16(rx);
  h = __bfloat16_as_ushort(hx);
  l = __bfloat16_as_ushort(lx);
}
// reconstruct fp32 pair from split uint2 (exact bf16->f32 via bit shift)
__device__ __forceinline__ float bflo(uint32_t v){ return __uint_as_float(v << 16); }
__device__ __forceinline__ float bfhi(uint32_t v){ return __uint_as_float(v & 0xffff0000u); }
__device__ __forceinline__ float2 unsplit(uint2 u){
  return make_float2(bflo(u.x) + bflo(u.y), bfhi(u.x) + bfhi(u.y));
}

#define MMA(c, a, bb0, bb1) \
  asm volatile("mma.sync.aligned.m16n8k16.row.col.f32.bf16.bf16.f32 " \
    "{%0,%1,%2,%3}, {%4,%5,%6,%7}, {%8,%9}, {%0,%1,%2,%3};" \
    : "+f"((c)[0]),"+f"((c)[1]),"+f"((c)[2]),"+f"((c)[3]) \
    : "r"((a)[0]),"r"((a)[1]),"r"((a)[2]),"r"((a)[3]), "r"(bb0),"r"(bb1))

__device__ __forceinline__ float lrelu(float x){ return (x > 0.f) ? x : 0.2f*x; }

// ---------------- K0: weight split ----------------
__global__ __launch_bounds__(256) void k0_conv(
    const float* __restrict__ gw1,  const float* __restrict__ gw2,
    const float* __restrict__ g2w1, const float* __restrict__ g2w2,
    const float* __restrict__ lw1,  const float* __restrict__ lw2,
    const float* __restrict__ lw3)
{
  int y = blockIdx.y;
  int e = blockIdx.x*256 + threadIdx.x;
  if (y < 2){
    const float* w1 = y ? g2w1 : gw1;
    const float* w2 = y ? g2w2 : gw2;
    if (e < 16384){
      int k = e >> 6, n = e & 63;
      unsigned short h,l; split_one(w1[e], h, l);
      g_gfW1h[y][n*256+k] = h; g_gfW1l[y][n*256+k] = l;
    } else if (e < 24576){
      int e2 = e - 16384;
      int k = e2 >> 7, n = e2 & 127;
      unsigned short h,l; split_one(w2[e2], h, l);
      g_gfW2h[y][n*64+k] = h; g_gfW2l[y][n*64+k] = l;
    }
  } else {
    if (e < 24576){
      int k = e >> 6, n = e & 63;
      unsigned short h,l; split_one(lw1[e], h, l);
      g_llW1h[n*384+k] = h; g_llW1l[n*384+k] = l;
    } else if (e < 28672){
      int e2 = e - 24576;
      int k = e2 >> 6, n = e2 & 63;
      unsigned short h,l; split_one(lw2[e2], h, l);
      g_llW2h[n*64+k] = h; g_llW2l[n*64+k] = l;
    } else if (e < 36864){
      int e2 = e - 28672;
      int k = e2 >> 7, n = e2 & 127;
      unsigned short h,l; split_one(lw3[e2], h, l);
      g_llW3h[n*64+k] = h; g_llW3l[n*64+k] = l;
    }
  }
}

// ---------------- K1: rowwise pre (writes split planes) ----------------
__global__ __launch_bounds__(256) void k1_pre(
    const float* __restrict__ L, const float* __restrict__ A,
    const float* __restrict__ V, const float* __restrict__ attw,
    const float* __restrict__ attb)
{
  int gw   = (int)((blockIdx.x*blockDim.x + threadIdx.x) >> 5);
  int lane = threadIdx.x & 31;
  size_t base = (size_t)gw*DD + lane*4;
  size_t pbase = (size_t)gw*64 + lane*2;

  float4 av = *(const float4*)(A+base);
  float4 vv = *(const float4*)(V+base);
  float4 lv = *(const float4*)(L+base);
  float4 wv = *(const float4*)(attw + lane*4);
  float bb = attb[0];

  float sa = fast_tanh(wsum(dot4(av,wv)) + bb);
  float sv = fast_tanh(wsum(dot4(vv,wv)) + bb);
  float sl = fast_tanh(wsum(dot4(lv,wv)) + bb);

  float4 u;
  u.x = (sa*av.x + sv*vv.x + sl*lv.x)*(1.0f/3.0f);
  u.y = (sa*av.y + sv*vv.y + sl*lv.y)*(1.0f/3.0f);
  u.z = (sa*av.z + sv*vv.z + sl*lv.z)*(1.0f/3.0f);
  u.w = (sa*av.w + sv*vv.w + sl*lv.w)*(1.0f/3.0f);
  g_sUni[pbase]   = split_u2(u.x, u.y);
  g_sUni[pbase+1] = split_u2(u.z, u.w);

  float m = wmax(max4(av));
  float4 pa = make_float4(fast_exp(av.x-m),fast_exp(av.y-m),fast_exp(av.z-m),fast_exp(av.w-m));
  float inv = 1.0f/wsum(sum4(pa));
  pa.x*=inv; pa.y*=inv; pa.z*=inv; pa.w*=inv;
  m = wmax(max4(vv));
  float4 pv = make_float4(fast_exp(vv.x-m),fast_exp(vv.y-m),fast_exp(vv.z-m),fast_exp(vv.w-m));
  inv = 1.0f/wsum(sum4(pv));
  pv.x*=inv; pv.y*=inv; pv.z*=inv; pv.w*=inv;
  m = wmax(max4(lv));
  float4 pl = make_float4(fast_exp(lv.x-m),fast_exp(lv.y-m),fast_exp(lv.z-m),fast_exp(lv.w-m));
  inv = 1.0f/wsum(sum4(pl));
  pl.x*=inv; pl.y*=inv; pl.z*=inv; pl.w*=inv;

  g_sPa[pbase]   = split_u2(pa.x, pa.y);
  g_sPa[pbase+1] = split_u2(pa.z, pa.w);
  g_sPv[pbase]   = split_u2(pv.x, pv.y);
  g_sPv[pbase+1] = split_u2(pv.z, pv.w);
  g_sPl[pbase]   = split_u2(pl.x, pl.y);
  g_sPl[pbase+1] = split_u2(pl.z, pl.w);

  float dav = wsum(dot4(pa,pv));
  float dal = wsum(dot4(pa,pl));
  float dvl = wsum(dot4(pv,pl));

  float sav = (sa+sv)/(dav+0.5f);
  float sal = (sa+sl)/(dal+0.5f);
  float svl = (sl+sv)/(dvl+0.5f);

  float m3 = fmaxf(sav,fmaxf(sal,svl));
  float e0 = fast_exp(sav-m3), e1 = fast_exp(sal-m3), e2 = fast_exp(svl-m3);
  float r3 = 1.0f/(e0+e1+e2);

  if (lane==0){
    float* s = g_s + (size_t)gw*16;
    s[0]=sa; s[1]=sv; s[2]=sl;
    s[3]=sav; s[4]=sal; s[5]=svl;
    s[6]=e0*r3; s[7]=e1*r3; s[8]=e2*r3;
  }
}

// ---------------- fused 2-layer MLP via mma.sync bf16x3, pre-split inputs ----------------
#define SMEM_MLP 105216

__device__ __forceinline__ void mlp2_mma(
    const uint2* __restrict__ x1, const uint2* __restrict__ x2,
    const float* __restrict__ b1, const float* __restrict__ b2,
    const unsigned short* __restrict__ w1h_g, const unsigned short* __restrict__ w1l_g,
    const unsigned short* __restrict__ w2h_g, const unsigned short* __restrict__ w2l_g,
    float* __restrict__ out, int row0, int n2slot)
{
  float* b1s = (float*)(smem_raw);
  float* b2s = (float*)(smem_raw + 256);
  unsigned short* W1h = (unsigned short*)(smem_raw + 768);
  unsigned short* W1l = W1h + 16896;
  unsigned short* W2h = W1l + 16896;
  unsigned short* W2l = W2h + 9216;

  int tid = threadIdx.x;

  #pragma unroll
  for (int idx = tid; idx < 2048; idx += 256){
    int row = idx >> 5, j = idx & 31;
    *((uint4*)(W1h + row*264) + j) = ((const uint4*)w1h_g)[idx];
    *((uint4*)(W1l + row*264) + j) = ((const uint4*)w1l_g)[idx];
  }
  #pragma unroll
  for (int idx = tid; idx < 1024; idx += 256){
    int row = idx >> 3, j = idx & 7;
    *((uint4*)(W2h + row*72) + j) = ((const uint4*)w2h_g)[idx];
    *((uint4*)(W2l + row*72) + j) = ((const uint4*)w2l_g)[idx];
  }
  if (tid < 64)  b1s[tid] = b1[tid];
  if (tid < 128) b2s[tid] = b2[tid];
  __syncthreads();

  int w = tid >> 5, lane = tid & 31;
  int g = lane >> 2, tg = lane & 3;
  int r0 = row0 + w*16 + g;
  int r1 = r0 + 8;

  // -------- stage 1 --------
  float acc[8][4];
  #pragma unroll
  for (int i=0;i<8;i++){ acc[i][0]=0.f; acc[i][1]=0.f; acc[i][2]=0.f; acc[i][3]=0.f; }

  #pragma unroll 1
  for (int kk = 0; kk < 16; kk++){
    const uint2* sp = (kk < 8) ? x1 : x2;
    int pi = (kk & 7)*8 + tg;
    const uint2* p0 = sp + (size_t)r0*64 + pi;
    const uint2* p1 = sp + (size_t)r1*64 + pi;
    uint2 u00 = p0[0], u01 = p0[4];
    uint2 u10 = p1[0], u11 = p1[4];
    uint32_t ah[4], al[4];
    ah[0]=u00.x; al[0]=u00.y;
    ah[1]=u10.x; al[1]=u10.y;
    ah[2]=u01.x; al[2]=u01.y;
    ah[3]=u11.x; al[3]=u11.y;
    int kb = kk*16 + tg*2;
    #pragma unroll
    for (int nt = 0; nt < 8; nt++){
      const unsigned short* bp = W1h + (nt*8+g)*264 + kb;
      const unsigned short* bq = W1l + (nt*8+g)*264 + kb;
      uint32_t bh0 = *(const uint32_t*)bp;
      uint32_t bh1 = *(const uint32_t*)(bp + 8);
      uint32_t bl0 = *(const uint32_t*)bq;
      uint32_t bl1 = *(const uint32_t*)(bq + 8);
      MMA(acc[nt], ah, bh0, bh1);
      MMA(acc[nt], ah, bl0, bl1);
      MMA(acc[nt], al, bh0, bh1);
    }
  }

  // -------- H = lrelu(acc + b1) -> frags --------
  uint32_t hh[4][4], hl[4][4];
  #pragma unroll
  for (int kt = 0; kt < 4; kt++){
    float* t0 = acc[2*kt];
    float* t1 = acc[2*kt+1];
    int c0 = kt*16 + tg*2;
    float bA = b1s[c0], bB = b1s[c0+1], bC = b1s[c0+8], bD = b1s[c0+9];
    split_pack2(lrelu(t0[0]+bA), lrelu(t0[1]+bB), hh[kt][0], hl[kt][0]);
    split_pack2(lrelu(t0[2]+bA), lrelu(t0[3]+bB), hh[kt][1], hl[kt][1]);
    split_pack2(lrelu(t1[0]+bC), lrelu(t1[1]+bD), hh[kt][2], hl[kt][2]);
    split_pack2(lrelu(t1[2]+bC), lrelu(t1[3]+bD), hh[kt][3], hl[kt][3]);
  }

  // -------- stage 2 --------
  float scv0 = 0.f, scv1 = 0.f;
  if (n2slot >= 0){
    scv0 = g_s[(size_t)r0*16 + n2slot];
    scv1 = g_s[(size_t)r1*16 + n2slot];
  }
  #pragma unroll 1
  for (int nh = 0; nh < 2; nh++){
    float acc2[8][4];
    #pragma unroll
    for (int i=0;i<8;i++){ acc2[i][0]=0.f; acc2[i][1]=0.f; acc2[i][2]=0.f; acc2[i][3]=0.f; }
    #pragma unroll
    for (int nt = 0; nt < 8; nt++){
      int n = (nh*8+nt)*8 + g;
      #pragma unroll
      for (int kt = 0; kt < 4; kt++){
        const unsigned short* bp = W2h + n*72 + kt*16 + tg*2;
        const unsigned short* bq = W2l + n*72 + kt*16 + tg*2;
        uint32_t bh0 = *(const uint32_t*)bp;
        uint32_t bh1 = *(const uint32_t*)(bp + 8);
        uint32_t bl0 = *(const uint32_t*)bq;
        uint32_t bl1 = *(const uint32_t*)(bq + 8);
        MMA(acc2[nt], hh[kt], bh0, bh1);
        MMA(acc2[nt], hh[kt], bl0, bl1);
        MMA(acc2[nt], hl[kt], bh0, bh1);
      }
    }
    #pragma unroll
    for (int nt = 0; nt < 8; nt++){
      int col = (nh*8+nt)*8 + tg*2;
      float v0 = fast_tanh(acc2[nt][0] + b2s[col]);
      float v1 = fast_tanh(acc2[nt][1] + b2s[col+1]);
      float v2 = fast_tanh(acc2[nt][2] + b2s[col]);
      float v3 = fast_tanh(acc2[nt][3] + b2s[col+1]);
      if (n2slot >= 0){
        v0 = fast_tanh(scv0*v0); v1 = fast_tanh(scv0*v1);
        v2 = fast_tanh(scv1*v2); v3 = fast_tanh(scv1*v3);
      }
      *(float2*)(out + (size_t)r0*DD + col) = make_float2(v0, v1);
      *(float2*)(out + (size_t)r1*DD + col) = make_float2(v2, v3);
    }
  }
}

__global__ __launch_bounds__(256) void k2_tc(const float* __restrict__ b1, const float* __restrict__ b2)
{
  const uint2 *x1, *x2;
  int p = blockIdx.y;
  if (p==0){ x1=g_sPa; x2=g_sPv; }
  else if (p==1){ x1=g_sPa; x2=g_sPl; }
  else { x1=g_sPv; x2=g_sPl; }
  mlp2_mma(x1, x2, b1, b2, g_gfW1h[0], g_gfW1l[0], g_gfW2h[0], g_gfW2l[0],
           g_G + (size_t)p*SLOT, blockIdx.x*128, -1);
}

__global__ __launch_bounds__(256) void k4_tc(const float* __restrict__ b1, const float* __restrict__ b2)
{
  const uint2 *x1, *x2;
  int p = blockIdx.y;
  switch(p){
    case 0: x1=g_sAV; x2=g_sVL; break;
    case 1: x1=g_sAV; x2=g_sAL; break;
    case 2: x1=g_sVL; x2=g_sAL; break;
    case 3: x1=g_sAV; x2=g_sPl; break;
    case 4: x1=g_sAL; x2=g_sPv; break;
    default:x1=g_sVL; x2=g_sPa; break;
  }
  mlp2_mma(x1, x2, b1, b2, g_gfW1h[1], g_gfW1l[1], g_gfW2h[1], g_gfW2l[1],
           g_G2 + (size_t)p*SLOT, blockIdx.x*128, 9+p);
}

// ---------------- K3: rowwise mid (reads split P, writes split AV/AL/VL/bi) ----------------
__global__ __launch_bounds__(256) void k3_mid()
{
  int gw   = (int)((blockIdx.x*blockDim.x + threadIdx.x) >> 5);
  int lane = threadIdx.x & 31;
  size_t base = (size_t)gw*DD + lane*4;
  size_t pbase = (size_t)gw*64 + lane*2;

  float4 gav = *(const float4*)(g_G + base);
  float4 gal = *(const float4*)(g_G + (size_t)SLOT + base);
  float4 gvl = *(const float4*)(g_G + 2*(size_t)SLOT + base);

  float2 t0, t1;
  t0 = unsplit(g_sPa[pbase]); t1 = unsplit(g_sPa[pbase+1]);
  float4 pa = make_float4(t0.x, t0.y, t1.x, t1.y);
  t0 = unsplit(g_sPv[pbase]); t1 = unsplit(g_sPv[pbase+1]);
  float4 pv = make_float4(t0.x, t0.y, t1.x, t1.y);
  t0 = unsplit(g_sPl[pbase]); t1 = unsplit(g_sPl[pbase+1]);
  float4 pl = make_float4(t0.x, t0.y, t1.x, t1.y);

  float m, inv;
  m = wmax(max4(gav));
  float4 A2 = make_float4(fast_exp(gav.x-m),fast_exp(gav.y-m),fast_exp(gav.z-m),fast_exp(gav.w-m));
  inv = 1.0f/wsum(sum4(A2)); A2.x*=inv; A2.y*=inv; A2.z*=inv; A2.w*=inv;
  m = wmax(max4(gal));
  float4 L2 = make_float4(fast_exp(gal.x-m),fast_exp(gal.y-m),fast_exp(gal.z-m),fast_exp(gal.w-m));
  inv = 1.0f/wsum(sum4(L2)); L2.x*=inv; L2.y*=inv; L2.z*=inv; L2.w*=inv;
  m = wmax(max4(gvl));
  float4 V2 = make_float4(fast_exp(gvl.x-m),fast_exp(gvl.y-m),fast_exp(gvl.z-m),fast_exp(gvl.w-m));
  inv = 1.0f/wsum(sum4(V2)); V2.x*=inv; V2.y*=inv; V2.z*=inv; V2.w*=inv;

  float d0 = wsum(dot4(A2,V2));
  float d1 = wsum(dot4(A2,L2));
  float d2 = wsum(dot4(L2,V2));
  float d3 = wsum(dot4(A2,pl));
  float d4 = wsum(dot4(L2,pv));
  float d5 = wsum(dot4(V2,pa));

  const float* s = g_s + (size_t)gw*16;
  float sa1=s[0], sv1=s[1], sl1=s[2], sav=s[3], sal=s[4], svl=s[5];
  float nm0=s[6], nm1=s[7], nm2=s[8];

  float e0=(sav+svl)/(d0+0.5f);
  float e1=(sav+sal)/(d1+0.5f);
  float e2=(sal+svl)/(d2+0.5f);
  float e3=(sav+sl1)/(d3+0.5f);
  float e4=(sal+sv1)/(d4+0.5f);
  float e5=(sa1+svl)/(d5+0.5f);
  float mm = fmaxf(fmaxf(fmaxf(e0,e1),fmaxf(e2,e3)),fmaxf(e4,e5));
  float x0=fast_exp(e0-mm),x1=fast_exp(e1-mm),x2=fast_exp(e2-mm);
  float x3=fast_exp(e3-mm),x4=fast_exp(e4-mm),x5=fast_exp(e5-mm);
  float ri = 1.0f/(x0+x1+x2+x3+x4+x5);
  if (lane==0){
    float* sw = g_s + (size_t)gw*16;
    sw[9]=x0*ri; sw[10]=x1*ri; sw[11]=x2*ri; sw[12]=x3*ri; sw[13]=x4*ri; sw[14]=x5*ri;
  }

  float4 AV = make_float4(fast_tanh(nm0*gav.x),fast_tanh(nm0*gav.y),fast_tanh(nm0*gav.z),fast_tanh(nm0*gav.w));
  float4 AL = make_float4(fast_tanh(nm1*gal.x),fast_tanh(nm1*gal.y),fast_tanh(nm1*gal.z),fast_tanh(nm1*gal.w));
  float4 VL = make_float4(fast_tanh(nm2*gvl.x),fast_tanh(nm2*gvl.y),fast_tanh(nm2*gvl.z),fast_tanh(nm2*gvl.w));

  g_sAV[pbase]   = split_u2(AV.x, AV.y);
  g_sAV[pbase+1] = split_u2(AV.z, AV.w);
  g_sAL[pbase]   = split_u2(AL.x, AL.y);
  g_sAL[pbase+1] = split_u2(AL.z, AL.w);
  g_sVL[pbase]   = split_u2(VL.x, VL.y);
  g_sVL[pbase+1] = split_u2(VL.z, VL.w);

  float4 bi = make_float4(AV.x+AL.x+VL.x, AV.y+AL.y+VL.y, AV.z+AL.z+VL.z, AV.w+AL.w+VL.w);
  g_sBi[pbase]   = split_u2(bi.x, bi.y);
  g_sBi[pbase+1] = split_u2(bi.z, bi.w);
}

// ---------------- K6: fused 3-layer head ----------------
#define SMEM_K6 156672

__global__ __launch_bounds__(256) void k6_tc(
    const float* __restrict__ b1, const float* __restrict__ b2,
    const float* __restrict__ b3, float* __restrict__ out)
{
  float* b1s = (float*)(smem_raw);
  float* b2s = (float*)(smem_raw + 256);
  float* b3s = (float*)(smem_raw + 512);
  unsigned short* W1h = (unsigned short*)(smem_raw + 1024);
  unsigned short* W1l = W1h + 25088;
  unsigned short* W2h = W1l + 25088;
  unsigned short* W2l = W2h + 4608;
  unsigned short* W3h = W2l + 4608;
  unsigned short* W3l = W3h + 9216;

  int tid = threadIdx.x;
  int row0 = blockIdx.x * 128;

  #pragma unroll
  for (int idx = tid; idx < 3072; idx += 256){
    int row = idx / 48, j = idx % 48;
    *((uint4*)(W1h + row*392) + j) = ((const uint4*)g_llW1h)[idx];
    *((uint4*)(W1l + row*392) + j) = ((const uint4*)g_llW1l)[idx];
  }
  #pragma unroll
  for (int idx = tid; idx < 512; idx += 256){
    int row = idx >> 3, j = idx & 7;
    *((uint4*)(W2h + row*72) + j) = ((const uint4*)g_llW2h)[idx];
    *((uint4*)(W2l + row*72) + j) = ((const uint4*)g_llW2l)[idx];
  }
  #pragma unroll
  for (int idx = tid; idx < 1024; idx += 256){
    int row = idx >> 3, j = idx & 7;
    *((uint4*)(W3h + row*72) + j) = ((const uint4*)g_llW3h)[idx];
    *((uint4*)(W3l + row*72) + j) = ((const uint4*)g_llW3l)[idx];
  }
  if (tid < 64)  b1s[tid] = b1[tid];
  if (tid < 64)  b2s[tid] = b2[tid];
  if (tid < 128) b3s[tid] = b3[tid];
  __syncthreads();

  int w = tid >> 5, lane = tid & 31;
  int g = lane >> 2, tg = lane & 3;
  int r0 = row0 + w*16 + g;
  int r1 = r0 + 8;

  // -------- layer 1: fusion[128x384] @ W1[384x64] --------
  float acc[8][4];
  #pragma unroll
  for (int i=0;i<8;i++){ acc[i][0]=0.f; acc[i][1]=0.f; acc[i][2]=0.f; acc[i][3]=0.f; }

  #pragma unroll 1
  for (int kk = 0; kk < 24; kk++){
    int ch = kk >> 3;
    uint32_t ah[4], al[4];
    if (ch < 2){
      const uint2* sp = (ch == 0) ? g_sUni : g_sBi;
      int pi = (kk & 7)*8 + tg;
      const uint2* p0 = sp + (size_t)r0*64 + pi;
      const uint2* p1 = sp + (size_t)r1*64 + pi;
      uint2 u00 = p0[0], u01 = p0[4];
      uint2 u10 = p1[0], u11 = p1[4];
      ah[0]=u00.x; al[0]=u00.y;
      ah[1]=u10.x; al[1]=u10.y;
      ah[2]=u01.x; al[2]=u01.y;
      ah[3]=u11.x; al[3]=u11.y;
    } else {
      int cc = (kk & 7)*16 + tg*2;
      size_t o0 = (size_t)r0*DD + cc;
      size_t o1 = (size_t)r1*DD + cc;
      float2 v00 = *(const float2*)(g_G2 + o0);
      float2 v01 = *(const float2*)(g_G2 + o0 + 8);
      float2 v10 = *(const float2*)(g_G2 + o1);
      float2 v11 = *(const float2*)(g_G2 + o1 + 8);
      #pragma unroll
      for (int p = 1; p < 6; p++){
        size_t po = (size_t)p*SLOT;
        float2 q;
        q = *(const float2*)(g_G2 + po + o0);     v00.x+=q.x; v00.y+=q.y;
        q = *(const float2*)(g_G2 + po + o0 + 8); v01.x+=q.x; v01.y+=q.y;
        q = *(const float2*)(g_G2 + po + o1);     v10.x+=q.x; v10.y+=q.y;
        q = *(const float2*)(g_G2 + po + o1 + 8); v11.x+=q.x; v11.y+=q.y;
      }
      split_pack2(v00.x, v00.y, ah[0], al[0]);
      split_pack2(v10.x, v10.y, ah[1], al[1]);
      split_pack2(v01.x, v01.y, ah[2], al[2]);
      split_pack2(v11.x, v11.y, ah[3], al[3]);
    }
    int kb = kk*16 + tg*2;
    #pragma unroll
    for (int nt = 0; nt < 8; nt++){
      const unsigned short* bp = W1h + (nt*8+g)*392 + kb;
      const unsigned short* bq = W1l + (nt*8+g)*392 + kb;
      uint32_t bh0 = *(const uint32_t*)bp;
      uint32_t bh1 = *(const uint32_t*)(bp + 8);
      uint32_t bl0 = *(const uint32_t*)bq;
      uint32_t bl1 = *(const uint32_t*)(bq + 8);
      MMA(acc[nt], ah, bh0, bh1);
      MMA(acc[nt], ah, bl0, bl1);
      MMA(acc[nt], al, bh0, bh1);
    }
  }

  uint32_t hh[4][4], hl[4][4];
  #pragma unroll
  for (int kt = 0; kt < 4; kt++){
    float* t0 = acc[2*kt];
    float* t1 = acc[2*kt+1];
    int c0 = kt*16 + tg*2;
    float bA = b1s[c0], bB = b1s[c0+1], bC = b1s[c0+8], bD = b1s[c0+9];
    split_pack2(fast_tanh(t0[0]+bA), fast_tanh(t0[1]+bB), hh[kt][0], hl[kt][0]);
    split_pack2(fast_tanh(t0[2]+bA), fast_tanh(t0[3]+bB), hh[kt][1], hl[kt][1]);
    split_pack2(fast_tanh(t1[0]+bC), fast_tanh(t1[1]+bD), hh[kt][2], hl[kt][2]);
    split_pack2(fast_tanh(t1[2]+bC), fast_tanh(t1[3]+bD), hh[kt][3], hl[kt][3]);
  }

  // -------- layer 2 --------
  #pragma unroll
  for (int i=0;i<8;i++){ acc[i][0]=0.f; acc[i][1]=0.f; acc[i][2]=0.f; acc[i][3]=0.f; }
  #pragma unroll
  for (int nt = 0; nt < 8; nt++){
    int n = nt*8 + g;
    #pragma unroll
    for (int kt = 0; kt < 4; kt++){
      const unsigned short* bp = W2h + n*72 + kt*16 + tg*2;
      const unsigned short* bq = W2l + n*72 + kt*16 + tg*2;
      uint32_t bh0 = *(const uint32_t*)bp;
      uint32_t bh1 = *(const uint32_t*)(bp + 8);
      uint32_t bl0 = *(const uint32_t*)bq;
      uint32_t bl1 = *(const uint32_t*)(bq + 8);
      MMA(acc[nt], hh[kt], bh0, bh1);
      MMA(acc[nt], hh[kt], bl0, bl1);
      MMA(acc[nt], hl[kt], bh0, bh1);
    }
  }
  #pragma unroll
  for (int kt = 0; kt < 4; kt++){
    float* t0 = acc[2*kt];
    float* t1 = acc[2*kt+1];
    int c0 = kt*16 + tg*2;
    float bA = b2s[c0], bB = b2s[c0+1], bC = b2s[c0+8], bD = b2s[c0+9];
    split_pack2(fast_tanh(t0[0]+bA), fast_tanh(t0[1]+bB), hh[kt][0], hl[kt][0]);
    split_pack2(fast_tanh(t0[2]+bA), fast_tanh(t0[3]+bB), hh[kt][1], hl[kt][1]);
    split_pack2(fast_tanh(t1[0]+bC), fast_tanh(t1[1]+bD), hh[kt][2], hl[kt][2]);
    split_pack2(fast_tanh(t1[2]+bC), fast_tanh(t1[3]+bD), hh[kt][3], hl[kt][3]);
  }

  // -------- layer 3 --------
  #pragma unroll 1
  for (int nh = 0; nh < 2; nh++){
    float acc2[8][4];
    #pragma unroll
    for (int i=0;i<8;i++){ acc2[i][0]=0.f; acc2[i][1]=0.f; acc2[i][2]=0.f; acc2[i][3]=0.f; }
    #pragma unroll
    for (int nt = 0; nt < 8; nt++){
      int n = (nh*8+nt)*8 + g;
      #pragma unroll
      for (int kt = 0; kt < 4; kt++){
        const unsigned short* bp = W3h + n*72 + kt*16 + tg*2;
        const unsigned short* bq = W3l + n*72 + kt*16 + tg*2;
        uint32_t bh0 = *(const uint32_t*)bp;
        uint32_t bh1 = *(const uint32_t*)(bp + 8);
        uint32_t bl0 = *(const uint32_t*)bq;
        uint32_t bl1 = *(const uint32_t*)(bq + 8);
        MMA(acc2[nt], hh[kt], bh0, bh1);
        MMA(acc2[nt], hh[kt], bl0, bl1);
        MMA(acc2[nt], hl[kt], bh0, bh1);
      }
    }
    #pragma unroll
    for (int nt = 0; nt < 8; nt++){
      int col = (nh*8+nt)*8 + tg*2;
      float v0 = fast_tanh(acc2[nt][0] + b3s[col]);
      float v1 = fast_tanh(acc2[nt][1] + b3s[col+1]);
      float v2 = fast_tanh(acc2[nt][2] + b3s[col]);
      float v3 = fast_tanh(acc2[nt][3] + b3s[col+1]);
      *(float2*)(out + (size_t)r0*DD + col) = make_float2(v0, v1);
      *(float2*)(out + (size_t)r1*DD + col) = make_float2(v2, v3);
    }
  }
}

// ---------------- launch ----------------
extern "C" void kernel_launch(void* const* d_in, const int* in_sizes, int n_in,
                              void* d_out, int out_size)
{
  (void)in_sizes; (void)n_in; (void)out_size;
  const float* L     = (const float*)d_in[0];
  const float* A     = (const float*)d_in[1];
  const float* V     = (const float*)d_in[2];
  const float* attw  = (const float*)d_in[3];
  const float* attb  = (const float*)d_in[4];
  const float* gfw1  = (const float*)d_in[5];
  const float* gfb1  = (const float*)d_in[6];
  const float* gfw2  = (const float*)d_in[7];
  const float* gfb2  = (const float*)d_in[8];
  const float* gf2w1 = (const float*)d_in[9];
  const float* gf2b1 = (const float*)d_in[10];
  const float* gf2w2 = (const float*)d_in[11];
  const float* gf2b2 = (const float*)d_in[12];
  const float* llw1  = (const float*)d_in[13];
  const float* llb1  = (const float*)d_in[14];
  const float* llw2  = (const float*)d_in[15];
  const float* llb2  = (const float*)d_in[16];
  const float* llw3  = (const float*)d_in[17];
  const float* llb3  = (const float*)d_in[18];
  float* out = (float*)d_out;

  cudaFuncSetAttribute(k2_tc, cudaFuncAttributeMaxDynamicSharedMemorySize, SMEM_MLP);
  cudaFuncSetAttribute(k4_tc, cudaFuncAttributeMaxDynamicSharedMemorySize, SMEM_MLP);
  cudaFuncSetAttribute(k6_tc, cudaFuncAttributeMaxDynamicSharedMemorySize, SMEM_K6);

  k0_conv<<<dim3(144,3), 256>>>(gfw1, gfw2, gf2w1, gf2w2, llw1, llw2, llw3);
  k1_pre<<<NB/8, 256>>>(L, A, V, attw, attb);
  k2_tc<<<dim3(NB/128, 3), 256, SMEM_MLP>>>(gfb1, gfb2);
  k3_mid<<<NB/8, 256>>>();
  k4_tc<<<dim3(NB/128, 6), 256, SMEM_MLP>>>(gf2b1, gf2b2);
  k6_tc<<<NB/128, 256, SMEM_K6>>>(llb1, llb2, llb3, out);
}